// round 4
// baseline (speedup 1.0000x reference)
#include <cuda_runtime.h>
#include <cuda_bf16.h>
#include <cstdint>

#define DINL __device__ __forceinline__

static constexpr int BB = 16, QQ = 2048, KK = 2048, DD = 512;

// ---- scratch (__device__ globals: allocation-free rule) ----
static __device__ float g_scores[(size_t)BB * QQ * KK];   // 256 MB
static __device__ float g_ctx[(size_t)BB * QQ * DD];      // 64 MB
static __device__ __nv_bfloat16 g_qh[(size_t)BB * QQ * DD], g_ql[(size_t)BB * QQ * DD];
static __device__ __nv_bfloat16 g_kh[(size_t)BB * KK * DD], g_kl[(size_t)BB * KK * DD];
static __device__ __nv_bfloat16 g_vth[(size_t)BB * DD * KK], g_vtl[(size_t)BB * DD * KK];
static __device__ __nv_bfloat16 g_wh[(size_t)BB * QQ * KK], g_wl[(size_t)BB * QQ * KK];

// ---- helpers ----
DINL uint32_t smem_u32(const void* p) {
    uint32_t a;
    asm("{ .reg .u64 t; cvta.to.shared.u64 t, %1; cvt.u32.u64 %0, t; }" : "=r"(a) : "l"(p));
    return a;
}
DINL void cpa16(uint32_t d, const void* s) {
    asm volatile("cp.async.cg.shared.global [%0],[%1],16;" ::"r"(d), "l"(s));
}
DINL void cpa_commit() { asm volatile("cp.async.commit_group;" ::: "memory"); }
DINL void ldx4(uint32_t* r, uint32_t a) {
    asm volatile("ldmatrix.sync.aligned.m8n8.x4.shared.b16 {%0,%1,%2,%3},[%4];"
                 : "=r"(r[0]), "=r"(r[1]), "=r"(r[2]), "=r"(r[3])
                 : "r"(a));
}
DINL void mma16816(float* d, const uint32_t* a, const uint32_t* b) {
    asm volatile(
        "mma.sync.aligned.m16n8k16.row.col.f32.bf16.bf16.f32 "
        "{%0,%1,%2,%3},{%4,%5,%6,%7},{%8,%9},{%0,%1,%2,%3};"
        : "+f"(d[0]), "+f"(d[1]), "+f"(d[2]), "+f"(d[3])
        : "r"(a[0]), "r"(a[1]), "r"(a[2]), "r"(a[3]), "r"(b[0]), "r"(b[1]));
}

struct alignas(8) B4 { __nv_bfloat16 a, b, c, d; };
DINL void split1(float x, __nv_bfloat16& h, __nv_bfloat16& l) {
    h = __float2bfloat16_rn(x);
    l = __float2bfloat16_rn(x - __bfloat162float(h));
}
DINL void split4(float4 f, B4& h, B4& l) {
    split1(f.x, h.a, l.a); split1(f.y, h.b, l.b);
    split1(f.z, h.c, l.c); split1(f.w, h.d, l.d);
}

// ---- prep: fp32 -> bf16 hi/lo (grid covers n/4 float4s exactly) ----
__global__ void __launch_bounds__(256) cvt_split(const float* __restrict__ s,
                                                 __nv_bfloat16* __restrict__ hi,
                                                 __nv_bfloat16* __restrict__ lo) {
    const size_t i = (size_t)blockIdx.x * 256 + threadIdx.x;
    const float4 v = reinterpret_cast<const float4*>(s)[i];
    B4 h, l;
    split4(v, h, l);
    reinterpret_cast<B4*>(hi)[i] = h;
    reinterpret_cast<B4*>(lo)[i] = l;
}

// ---- V transpose: vt[b][d][k] = V[b][k][d], split to bf16 hi/lo ----
__global__ void __launch_bounds__(256) transpose_v(const float* __restrict__ v,
                                                   __nv_bfloat16* __restrict__ th,
                                                   __nv_bfloat16* __restrict__ tl) {
    __shared__ float t[32][33];
    const int b = blockIdx.z;
    const int d0 = blockIdx.x << 5, k0 = blockIdx.y << 5;
    const int tx = threadIdx.x & 31, ty = threadIdx.x >> 5;
#pragma unroll
    for (int i = ty; i < 32; i += 8)
        t[i][tx] = v[((size_t)b * KK + k0 + i) * DD + d0 + tx];
    __syncthreads();
#pragma unroll
    for (int i = ty; i < 32; i += 8) {
        const float x = t[tx][i];
        __nv_bfloat16 h, l;
        split1(x, h, l);
        const size_t o = ((size_t)b * DD + d0 + i) * KK + k0 + tx;
        th[o] = h;
        tl[o] = l;
    }
}

// ---- split-bf16 GEMM: O[M=128,N=128] tile = A[M,KTOT] @ B[N,KTOT]^T ----
// smem: 2 stages x 4 tiles (aHi,aLo,bHi,bLo), each tile 128 rows x 80B (32 bf16 + pad)
static constexpr int TROW = 80;           // bytes/row (pad for conflict-free ldmatrix)
static constexpr int TILE_B = 128 * TROW; // 10240
static constexpr int STAGE_B = 4 * TILE_B;
static constexpr int SMEM_B = 2 * STAGE_B; // 81920

DINL void load_stage(uint32_t sb, int stage, int kc, const __nv_bfloat16* const* gp,
                     int tid, int ktot) {
    const uint32_t base = sb + stage * STAGE_B;
#pragma unroll
    for (int t = 0; t < 4; t++) {
#pragma unroll
        for (int i = 0; i < 2; i++) {
            const int idx = i * 256 + tid;
            const int row = idx >> 2, c = idx & 3;
            cpa16(base + t * TILE_B + row * TROW + c * 16,
                  gp[t] + (size_t)row * ktot + kc * 32 + c * 8);
        }
    }
}

template <int KTOT, bool MASK>
__global__ void __launch_bounds__(256)
attn_gemm(const __nv_bfloat16* __restrict__ Ah, const __nv_bfloat16* __restrict__ Al,
          const __nv_bfloat16* __restrict__ Bh, const __nv_bfloat16* __restrict__ Bl,
          const int* __restrict__ lens, float* __restrict__ O, int nb, int ldout,
          float scale) {
    extern __shared__ __align__(128) char smem[];
    const uint32_t sb = smem_u32(smem);
    const int tid = threadIdx.x, lane = tid & 31, wid = tid >> 5;
    const int bn = blockIdx.x, bm = blockIdx.y, bz = blockIdx.z;
    const int warpM = (wid >> 2) * 64, warpN = (wid & 3) * 32;

    const size_t aOff = (size_t)bz * QQ * KTOT + (size_t)(bm * 128) * KTOT;
    const size_t bOff = (size_t)bz * nb * KTOT + (size_t)(bn * 128) * KTOT;
    const __nv_bfloat16* gp[4] = {Ah + aOff, Al + aOff, Bh + bOff, Bl + bOff};

    float acc[4][4][4];
#pragma unroll
    for (int i = 0; i < 4; i++)
#pragma unroll
        for (int j = 0; j < 4; j++)
#pragma unroll
            for (int c = 0; c < 4; c++) acc[i][j][c] = 0.f;

    constexpr int NCH = KTOT / 32;
    load_stage(sb, 0, 0, gp, tid, KTOT);
    cpa_commit();

    for (int kc = 0; kc < NCH; kc++) {
        const int cur = kc & 1;
        if (kc + 1 < NCH) {
            load_stage(sb, cur ^ 1, kc + 1, gp, tid, KTOT);
            cpa_commit();
            asm volatile("cp.async.wait_group 1;" ::: "memory");
        } else {
            asm volatile("cp.async.wait_group 0;" ::: "memory");
        }
        __syncthreads();

        const uint32_t tb = sb + cur * STAGE_B;
#pragma unroll
        for (int ks = 0; ks < 2; ks++) {
            uint32_t ah4[4][4], al4[4][4], bh2[4][2], bl2[4][2];
            const uint32_t aoffb = ((lane >> 4) * 8 + ks * 16) * 2;
#pragma unroll
            for (int i = 0; i < 4; i++) {
                const uint32_t rowb = (uint32_t)(warpM + i * 16 + (lane & 15)) * TROW;
                ldx4(ah4[i], tb + rowb + aoffb);
                ldx4(al4[i], tb + TILE_B + rowb + aoffb);
            }
            const int m = lane >> 3;
            const uint32_t koffb = ((m & 1) * 8 + ks * 16) * 2;
#pragma unroll
            for (int j = 0; j < 2; j++) {
                const uint32_t rowb =
                    (uint32_t)(warpN + (j * 2 + (m >> 1)) * 8 + (lane & 7)) * TROW;
                uint32_t r4[4];
                ldx4(r4, tb + 2 * TILE_B + rowb + koffb);
                bh2[2 * j][0] = r4[0]; bh2[2 * j][1] = r4[1];
                bh2[2 * j + 1][0] = r4[2]; bh2[2 * j + 1][1] = r4[3];
                ldx4(r4, tb + 3 * TILE_B + rowb + koffb);
                bl2[2 * j][0] = r4[0]; bl2[2 * j][1] = r4[1];
                bl2[2 * j + 1][0] = r4[2]; bl2[2 * j + 1][1] = r4[3];
            }
            // hi*hi, then cross terms (lo*lo dropped: ~2^-18)
#pragma unroll
            for (int i = 0; i < 4; i++)
#pragma unroll
                for (int j = 0; j < 4; j++) mma16816(acc[i][j], ah4[i], bh2[j]);
#pragma unroll
            for (int i = 0; i < 4; i++)
#pragma unroll
                for (int j = 0; j < 4; j++) mma16816(acc[i][j], ah4[i], bl2[j]);
#pragma unroll
            for (int i = 0; i < 4; i++)
#pragma unroll
                for (int j = 0; j < 4; j++) mma16816(acc[i][j], al4[i], bh2[j]);
        }
        __syncthreads();
    }

    // epilogue: c0,c1 -> (r, n..n+1); c2,c3 -> (r+8, n..n+1)
    const int len = MASK ? lens[bz] : 0;
    float* Ob = O + (size_t)bz * QQ * ldout;
    const float NEG = __int_as_float(0xff800000);
#pragma unroll
    for (int i = 0; i < 4; i++) {
        const int r0 = bm * 128 + warpM + i * 16 + (lane >> 2);
#pragma unroll
        for (int j = 0; j < 4; j++) {
            const int nc = bn * 128 + warpN + j * 8 + (lane & 3) * 2;
            float2 v0, v1;
            if (MASK) {
                v0.x = (nc >= len) ? NEG : acc[i][j][0] * scale;
                v0.y = (nc + 1 >= len) ? NEG : acc[i][j][1] * scale;
                v1.x = (nc >= len) ? NEG : acc[i][j][2] * scale;
                v1.y = (nc + 1 >= len) ? NEG : acc[i][j][3] * scale;
            } else {
                v0.x = acc[i][j][0]; v0.y = acc[i][j][1];
                v1.x = acc[i][j][2]; v1.y = acc[i][j][3];
            }
            *reinterpret_cast<float2*>(Ob + (size_t)r0 * ldout + nc) = v0;
            *reinterpret_cast<float2*>(Ob + (size_t)(r0 + 8) * ldout + nc) = v1;
        }
    }
}

// ---- row softmax (in-place fp32) + bf16 hi/lo weight copies ----
__global__ void __launch_bounds__(256) softmax_rows(float* __restrict__ sbf,
                                                    __nv_bfloat16* __restrict__ wh,
                                                    __nv_bfloat16* __restrict__ wl) {
    const size_t rowoff = (size_t)blockIdx.x * KK;
    float4* p = reinterpret_cast<float4*>(sbf + rowoff);
    const int tid = threadIdx.x;
    const float4 a = p[tid];
    const float4 c = p[tid + 256];

    __shared__ float shm[8], shs[8];
    float m = fmaxf(fmaxf(fmaxf(a.x, a.y), fmaxf(a.z, a.w)),
                    fmaxf(fmaxf(c.x, c.y), fmaxf(c.z, c.w)));
#pragma unroll
    for (int o = 16; o; o >>= 1) m = fmaxf(m, __shfl_xor_sync(0xffffffffu, m, o));
    if ((tid & 31) == 0) shm[tid >> 5] = m;
    __syncthreads();
    float M = shm[0];
#pragma unroll
    for (int i = 1; i < 8; i++) M = fmaxf(M, shm[i]);

    const float e0 = __expf(a.x - M), e1 = __expf(a.y - M), e2 = __expf(a.z - M),
                e3 = __expf(a.w - M);
    const float e4 = __expf(c.x - M), e5 = __expf(c.y - M), e6 = __expf(c.z - M),
                e7 = __expf(c.w - M);
    float s = ((e0 + e1) + (e2 + e3)) + ((e4 + e5) + (e6 + e7));
#pragma unroll
    for (int o = 16; o; o >>= 1) s += __shfl_xor_sync(0xffffffffu, s, o);
    if ((tid & 31) == 0) shs[tid >> 5] = s;
    __syncthreads();
    float S = 0.f;
#pragma unroll
    for (int i = 0; i < 8; i++) S += shs[i];
    const float inv = 1.0f / S;

    const float4 w0 = make_float4(e0 * inv, e1 * inv, e2 * inv, e3 * inv);
    const float4 w1 = make_float4(e4 * inv, e5 * inv, e6 * inv, e7 * inv);
    p[tid] = w0;
    p[tid + 256] = w1;

    B4 h0, l0, h1, l1;
    split4(w0, h0, l0);
    split4(w1, h1, l1);
    B4* ph = reinterpret_cast<B4*>(wh + rowoff);
    B4* pl = reinterpret_cast<B4*>(wl + rowoff);
    ph[tid] = h0; pl[tid] = l0;
    ph[tid + 256] = h1; pl[tid + 256] = l1;
}

// ---- launch ----
extern "C" void kernel_launch(void* const* d_in, const int* in_sizes, int n_in,
                              void* d_out, int out_size) {
    const float* fl[3] = {nullptr, nullptr, nullptr};
    const int* lens = nullptr;
    int fi = 0;
    for (int i = 0; i < n_in; i++) {
        if (in_sizes[i] == BB) lens = (const int*)d_in[i];
        else if (fi < 3) fl[fi++] = (const float*)d_in[i];
    }
    const float* q = fl[0];
    const float* k = fl[1];
    const float* v = fl[2];

    void* p;
    float *scores_g, *ctx_g;
    __nv_bfloat16 *qh, *ql, *kh, *kl, *vth, *vtl, *wh, *wl;
    cudaGetSymbolAddress(&p, g_scores); scores_g = (float*)p;
    cudaGetSymbolAddress(&p, g_ctx);    ctx_g = (float*)p;
    cudaGetSymbolAddress(&p, g_qh);  qh = (__nv_bfloat16*)p;
    cudaGetSymbolAddress(&p, g_ql);  ql = (__nv_bfloat16*)p;
    cudaGetSymbolAddress(&p, g_kh);  kh = (__nv_bfloat16*)p;
    cudaGetSymbolAddress(&p, g_kl);  kl = (__nv_bfloat16*)p;
    cudaGetSymbolAddress(&p, g_vth); vth = (__nv_bfloat16*)p;
    cudaGetSymbolAddress(&p, g_vtl); vtl = (__nv_bfloat16*)p;
    cudaGetSymbolAddress(&p, g_wh);  wh = (__nv_bfloat16*)p;
    cudaGetSymbolAddress(&p, g_wl);  wl = (__nv_bfloat16*)p;

    const size_t CTX = (size_t)BB * QQ * DD;  // 16,777,216
    const size_t W = (size_t)BB * QQ * KK;    // 67,108,864
    float* out = (float*)d_out;
    float *sbuf, *cbuf;
    if ((size_t)out_size >= CTX + W) { cbuf = out; sbuf = out + CTX; }
    else if ((size_t)out_size >= W)  { sbuf = out; cbuf = ctx_g; }
    else                             { cbuf = out; sbuf = scores_g; }

    cudaFuncSetAttribute(attn_gemm<DD, true>,
                         cudaFuncAttributeMaxDynamicSharedMemorySize, SMEM_B);
    cudaFuncSetAttribute(attn_gemm<KK, false>,
                         cudaFuncAttributeMaxDynamicSharedMemorySize, SMEM_B);

    const float scale = 0.044194173824159216f;  // 1/sqrt(512)

    cvt_split<<<16384, 256>>>(q, qh, ql);  // 16.8M elems / (256*4)
    cvt_split<<<16384, 256>>>(k, kh, kl);
    transpose_v<<<dim3(DD / 32, KK / 32, BB), 256>>>(v, vth, vtl);
    attn_gemm<DD, true><<<dim3(KK / 128, QQ / 128, BB), 256, SMEM_B>>>(
        qh, ql, kh, kl, lens, sbuf, KK, KK, scale);
    softmax_rows<<<BB * QQ, 256>>>(sbuf, wh, wl);
    attn_gemm<KK, false><<<dim3(DD / 128, QQ / 128, BB), 256, SMEM_B>>>(
        wh, wl, vth, vtl, nullptr, cbuf, DD, DD, 1.0f);
}